// round 7
// baseline (speedup 1.0000x reference)
#include <cuda_runtime.h>

// ForwardKinematicsLayer: SMPL 24-joint FK, B=262144 bodies.
// Inputs: local_rots [B,24,3,3] f32, root_pos [B,3] f32, offsets [24,3] f32
// Output: concat( global_pos [B,24,3], global_rots [B,24,3,3] ) f32
//
// Block = 128 threads staging, 64 bodies computing. All global traffic is
// coalesced scalar ld/st through a TRANSPOSED smem tile [element_row][body]
// with row stride 65 floats (65 mod 32 = 1 -> conflict-free staging; compute
// accesses are lane-consecutive -> conflict-free by construction). Compute is
// a fully-unrolled register FK chain (one thread per body); global rots
// overwrite the consumed local rots in smem in place.

#define NJ 24
#define NB 64                 // bodies per block
#define NT 128                // threads per block (2x staging parallelism)
#define SROW (NB + 1)         // 65
// rows: [0..215] local->global rots, [216..287] out pos, [288..290] root pos
#define SROWS 291
#define SMEM_BYTES (SROWS * SROW * 4)   // 75,660 B -> 3 blocks/SM (226,980 B < 228 KB)

extern __shared__ float sm[];

__global__ __launch_bounds__(NT)
void fk_kernel(const float* __restrict__ lr,
               const float* __restrict__ root,
               const float* __restrict__ off,
               float* __restrict__ out,
               int B)
{
    const int t  = threadIdx.x;
    const int b0 = blockIdx.x * NB;
    const int nb = min(NB, B - b0);

    // ---------- Phase 1: coalesced stage-in (transposed) ----------
    {
        // Root pos first so its LDGs enter the memory window early.
        const float* rsrc = root + (size_t)b0 * 3;
        for (int idx = t; idx < nb * 3; idx += NT) {
            int body = idx / 3;
            int c    = idx - body * 3;
            sm[(288 + c) * SROW + body] = rsrc[idx];
        }

        const float* src = lr + (size_t)b0 * (NJ * 9);
        const int total = nb * (NJ * 9);
        #pragma unroll 6
        for (int idx = t; idx < NB * (NJ * 9); idx += NT) {   // 108 iters
            if (idx < total) {
                int body = idx / 216;
                int c    = idx - body * 216;
                sm[c * SROW + body] = src[idx];    // LDG coalesced, STS stride 65
            }
        }
    }
    __syncthreads();

    // ---------- Phase 2: register FK chain, one thread per body ----------
    if (t < nb) {
        constexpr int PAR[NJ] = {-1, 0, 0, 0, 1, 2, 3, 4, 5, 6, 7, 8,
                                  9, 9, 9, 12, 13, 14, 16, 17, 18, 19, 20, 21};
        float gr[NJ][9];
        float gp[NJ][3];

        #pragma unroll
        for (int i = 0; i < 9; ++i)
            gr[0][i] = sm[i * SROW + t];            // rows 0..8 already = out rot[0]
        #pragma unroll
        for (int i = 0; i < 3; ++i) {
            gp[0][i] = sm[(288 + i) * SROW + t];
            sm[(216 + i) * SROW + t] = gp[0][i];    // out pos[0]
        }

        #pragma unroll
        for (int j = 1; j < NJ; ++j) {
            const int p = PAR[j];

            float l[9];
            #pragma unroll
            for (int i = 0; i < 9; ++i)
                l[i] = sm[(j * 9 + i) * SROW + t];

            const float o0 = __ldg(&off[j * 3 + 0]);
            const float o1 = __ldg(&off[j * 3 + 1]);
            const float o2 = __ldg(&off[j * 3 + 2]);

            #pragma unroll
            for (int i = 0; i < 3; ++i) {
                gp[j][i] = gp[p][i]
                         + gr[p][i * 3 + 0] * o0
                         + gr[p][i * 3 + 1] * o1
                         + gr[p][i * 3 + 2] * o2;
                sm[(216 + j * 3 + i) * SROW + t] = gp[j][i];
            }

            #pragma unroll
            for (int i = 0; i < 3; ++i) {
                const float a0 = gr[p][i * 3 + 0];
                const float a1 = gr[p][i * 3 + 1];
                const float a2 = gr[p][i * 3 + 2];
                #pragma unroll
                for (int k = 0; k < 3; ++k) {
                    const float v = a0 * l[0 + k] + a1 * l[3 + k] + a2 * l[6 + k];
                    gr[j][i * 3 + k] = v;
                    sm[(j * 9 + i * 3 + k) * SROW + t] = v;  // overwrite consumed l[j]
                }
            }
        }
    }
    __syncthreads();

    // ---------- Phase 3: coalesced stage-out ----------
    {
        float* pdst = out + (size_t)b0 * (NJ * 3);
        for (int idx = t; idx < nb * (NJ * 3); idx += NT) {
            int body = idx / 72;
            int c    = idx - body * 72;
            pdst[idx] = sm[(216 + c) * SROW + body];
        }
        float* rdst = out + (size_t)B * (NJ * 3) + (size_t)b0 * (NJ * 9);
        const int total = nb * (NJ * 9);
        #pragma unroll 6
        for (int idx = t; idx < NB * (NJ * 9); idx += NT) {
            if (idx < total) {
                int body = idx / 216;
                int c    = idx - body * 216;
                rdst[idx] = sm[c * SROW + body];
            }
        }
    }
}

extern "C" void kernel_launch(void* const* d_in, const int* in_sizes, int n_in,
                              void* d_out, int out_size)
{
    const float* lr   = (const float*)d_in[0];
    const float* root = (const float*)d_in[1];
    const float* off  = (const float*)d_in[2];

    const int B = in_sizes[0] / (NJ * 9);
    float* out = (float*)d_out;

    // Non-stream, idempotent host config (not captured; allowed under the rules).
    cudaFuncSetAttribute(fk_kernel, cudaFuncAttributeMaxDynamicSharedMemorySize,
                         SMEM_BYTES);

    const int blocks = (B + NB - 1) / NB;
    fk_kernel<<<blocks, NT, SMEM_BYTES>>>(lr, root, off, out, B);
}

// round 8
// speedup vs baseline: 1.3281x; 1.3281x over previous
#include <cuda_runtime.h>

// ForwardKinematicsLayer: SMPL 24-joint FK, B=262144 bodies.
// Inputs: local_rots [B,24,3,3] f32, root_pos [B,3] f32, offsets [24,3] f32
// Output: concat( global_pos [B,24,3], global_rots [B,24,3,3] ) f32
//
// Block = 256 threads staging, 64 bodies computing. All global traffic is
// coalesced scalar ld/st through a TRANSPOSED smem tile [element_row][body]
// with row stride 65 floats (conflict-free in every phase). Compute is a
// fully-unrolled register FK chain (one thread per body); global rots
// overwrite the consumed local rots in smem in place.
//
// R7 change: NT 128->256 at constant smem -> 24 warps/SM (was 12). Round-7
// ncu showed DRAM=35%, occ=18%: latency-bound, not bandwidth-bound. Doubling
// resident warps doubles in-flight LDGs. Full blocks take a guard-free path.

#define NJ 24
#define NB 64                 // bodies per block
#define NT 256                // threads per block
#define SROW (NB + 1)         // 65
// rows: [0..215] local->global rots, [216..287] out pos, [288..290] root pos
#define SROWS 291
#define SMEM_BYTES (SROWS * SROW * 4)   // 75,660 B -> 3 blocks/SM (226,980 B < 228 KB)

extern __shared__ float sm[];

__global__ __launch_bounds__(NT)
void fk_kernel(const float* __restrict__ lr,
               const float* __restrict__ root,
               const float* __restrict__ off,
               float* __restrict__ out,
               int B)
{
    const int t  = threadIdx.x;
    const int b0 = blockIdx.x * NB;
    const int nb = min(NB, B - b0);
    const bool full = (nb == NB);

    // ---------- Phase 1: coalesced stage-in (transposed) ----------
    {
        const float* rsrc = root + (size_t)b0 * 3;
        if (t < NB * 3) {                      // 192 < NT, single shot
            int body = t / 3;
            int c    = t - body * 3;
            if (full || body < nb)
                sm[(288 + c) * SROW + body] = rsrc[t];
        }

        const float* src = lr + (size_t)b0 * (NJ * 9);
        if (full) {
            #pragma unroll 6
            for (int idx = t; idx < NB * (NJ * 9); idx += NT) {  // 54 iters
                int body = idx / 216;
                int c    = idx - body * 216;
                sm[c * SROW + body] = src[idx];  // LDG coalesced, STS stride 65
            }
        } else {
            const int total = nb * (NJ * 9);
            #pragma unroll 6
            for (int idx = t; idx < NB * (NJ * 9); idx += NT) {
                if (idx < total) {
                    int body = idx / 216;
                    int c    = idx - body * 216;
                    sm[c * SROW + body] = src[idx];
                }
            }
        }
    }
    __syncthreads();

    // ---------- Phase 2: register FK chain, one thread per body ----------
    if (t < nb) {
        constexpr int PAR[NJ] = {-1, 0, 0, 0, 1, 2, 3, 4, 5, 6, 7, 8,
                                  9, 9, 9, 12, 13, 14, 16, 17, 18, 19, 20, 21};
        float gr[NJ][9];
        float gp[NJ][3];

        #pragma unroll
        for (int i = 0; i < 9; ++i)
            gr[0][i] = sm[i * SROW + t];            // rows 0..8 already = out rot[0]
        #pragma unroll
        for (int i = 0; i < 3; ++i) {
            gp[0][i] = sm[(288 + i) * SROW + t];
            sm[(216 + i) * SROW + t] = gp[0][i];    // out pos[0]
        }

        #pragma unroll
        for (int j = 1; j < NJ; ++j) {
            const int p = PAR[j];

            float l[9];
            #pragma unroll
            for (int i = 0; i < 9; ++i)
                l[i] = sm[(j * 9 + i) * SROW + t];

            const float o0 = __ldg(&off[j * 3 + 0]);
            const float o1 = __ldg(&off[j * 3 + 1]);
            const float o2 = __ldg(&off[j * 3 + 2]);

            #pragma unroll
            for (int i = 0; i < 3; ++i) {
                gp[j][i] = gp[p][i]
                         + gr[p][i * 3 + 0] * o0
                         + gr[p][i * 3 + 1] * o1
                         + gr[p][i * 3 + 2] * o2;
                sm[(216 + j * 3 + i) * SROW + t] = gp[j][i];
            }

            #pragma unroll
            for (int i = 0; i < 3; ++i) {
                const float a0 = gr[p][i * 3 + 0];
                const float a1 = gr[p][i * 3 + 1];
                const float a2 = gr[p][i * 3 + 2];
                #pragma unroll
                for (int k = 0; k < 3; ++k) {
                    const float v = a0 * l[0 + k] + a1 * l[3 + k] + a2 * l[6 + k];
                    gr[j][i * 3 + k] = v;
                    sm[(j * 9 + i * 3 + k) * SROW + t] = v;  // overwrite consumed l[j]
                }
            }
        }
    }
    __syncthreads();

    // ---------- Phase 3: coalesced stage-out ----------
    {
        float* pdst = out + (size_t)b0 * (NJ * 3);
        if (full) {
            if (t < NB * (NJ * 3)) {             // 4608? no: 64*72 = 4608 > 256
            }
            #pragma unroll 6
            for (int idx = t; idx < NB * (NJ * 3); idx += NT) {  // 18 iters
                int body = idx / 72;
                int c    = idx - body * 72;
                pdst[idx] = sm[(216 + c) * SROW + body];
            }
        } else {
            for (int idx = t; idx < nb * (NJ * 3); idx += NT) {
                int body = idx / 72;
                int c    = idx - body * 72;
                pdst[idx] = sm[(216 + c) * SROW + body];
            }
        }

        float* rdst = out + (size_t)B * (NJ * 3) + (size_t)b0 * (NJ * 9);
        if (full) {
            #pragma unroll 6
            for (int idx = t; idx < NB * (NJ * 9); idx += NT) {  // 54 iters
                int body = idx / 216;
                int c    = idx - body * 216;
                rdst[idx] = sm[c * SROW + body];
            }
        } else {
            const int total = nb * (NJ * 9);
            #pragma unroll 6
            for (int idx = t; idx < NB * (NJ * 9); idx += NT) {
                if (idx < total) {
                    int body = idx / 216;
                    int c    = idx - body * 216;
                    rdst[idx] = sm[c * SROW + body];
                }
            }
        }
    }
}

extern "C" void kernel_launch(void* const* d_in, const int* in_sizes, int n_in,
                              void* d_out, int out_size)
{
    const float* lr   = (const float*)d_in[0];
    const float* root = (const float*)d_in[1];
    const float* off  = (const float*)d_in[2];

    const int B = in_sizes[0] / (NJ * 9);
    float* out = (float*)d_out;

    // Non-stream, idempotent host config (not captured; allowed under the rules).
    cudaFuncSetAttribute(fk_kernel, cudaFuncAttributeMaxDynamicSharedMemorySize,
                         SMEM_BYTES);

    const int blocks = (B + NB - 1) / NB;
    fk_kernel<<<blocks, NT, SMEM_BYTES>>>(lr, root, off, out, B);
}